// round 8
// baseline (speedup 1.0000x reference)
#include <cuda_runtime.h>
#include <cstdint>

// Problem constants
#define S_LEN 2048
#define BATCH 2
#define NHEAD 16
#define HD    64
#define DM    1024
#define MROWS (BATCH * S_LEN)   // 4096

// Scratch (device globals: no allocations allowed)
__device__ float g_kv [MROWS * 2 * DM];   // k,v projections (tf32-rounded)
__device__ float g_q  [MROWS * DM];       // q projection   (tf32-rounded)
__device__ float g_att[MROWS * DM];       // attention out  (tf32-rounded)
__device__ float g_xt [MROWS * DM];       // tf32(x)
__device__ float g_yt [MROWS * DM];       // tf32(y)
__device__ float g_wkvt[DM * 2 * DM];     // tf32(Wkv)
__device__ float g_wqt [DM * DM];         // tf32(Wq)
__device__ float g_wot [DM * DM];         // tf32(Wo)

// ---------------------------------------------------------------------------
// helpers
// ---------------------------------------------------------------------------
__device__ __forceinline__ float f2tf(float x) {
    uint32_t r;
    asm("cvt.rna.tf32.f32 %0, %1;" : "=r"(r) : "f"(x));
    return __uint_as_float(r);
}

__device__ __forceinline__ void mma_tf32(float c[4],
                                         uint32_t a0, uint32_t a1, uint32_t a2, uint32_t a3,
                                         uint32_t b0, uint32_t b1) {
    asm volatile(
        "mma.sync.aligned.m16n8k8.row.col.f32.tf32.tf32.f32 "
        "{%0,%1,%2,%3}, {%4,%5,%6,%7}, {%8,%9}, {%0,%1,%2,%3};"
        : "+f"(c[0]), "+f"(c[1]), "+f"(c[2]), "+f"(c[3])
        : "r"(a0), "r"(a1), "r"(a2), "r"(a3), "r"(b0), "r"(b1));
}

__device__ __forceinline__ void cp16(uint32_t dst, const float* src) {
    asm volatile("cp.async.cg.shared.global [%0], [%1], 16;" :: "r"(dst), "l"(src));
}
__device__ __forceinline__ void cp_commit() {
    asm volatile("cp.async.commit_group;");
}
template<int N> __device__ __forceinline__ void cp_wait() {
    asm volatile("cp.async.wait_group %0;" :: "n"(N));
}

// ---------------------------------------------------------------------------
// Merged tf32 conversion pass (one launch for all 5 tensors)
// ---------------------------------------------------------------------------
#define N4_X  (MROWS * DM / 4)       // 1048576
#define N4_Y  (MROWS * DM / 4)       // 1048576
#define N4_KV (DM * 2 * DM / 4)      // 524288
#define N4_Q  (DM * DM / 4)          // 262144
#define N4_O  (DM * DM / 4)          // 262144
#define N4_TOT (N4_X + N4_Y + N4_KV + N4_Q + N4_O)

__global__ void conv_all(
    const float4* __restrict__ x,  const float4* __restrict__ y,
    const float4* __restrict__ wkv, const float4* __restrict__ wq,
    const float4* __restrict__ wo,
    float4* __restrict__ xt,  float4* __restrict__ yt,
    float4* __restrict__ wkvt, float4* __restrict__ wqt,
    float4* __restrict__ wot)
{
    int i = blockIdx.x * blockDim.x + threadIdx.x;
    const int stride = gridDim.x * blockDim.x;
    for (; i < N4_TOT; i += stride) {
        const float4* src; float4* dst; int j = i;
        if (j < N4_X)                  { src = x;   dst = xt;   }
        else if ((j -= N4_X)  < N4_Y)  { src = y;   dst = yt;   }
        else if ((j -= N4_Y)  < N4_KV) { src = wkv; dst = wkvt; }
        else if ((j -= N4_KV) < N4_Q)  { src = wq;  dst = wqt;  }
        else { j -= N4_Q;                src = wo;  dst = wot;  }
        float4 v = src[j];
        dst[j] = make_float4(f2tf(v.x), f2tf(v.y), f2tf(v.z), f2tf(v.w));
    }
}

// ---------------------------------------------------------------------------
// GEMM v3 (unchanged): C = A @ W + bias, cp.async 3-stage.
// ---------------------------------------------------------------------------
#define TBM 128
#define TBN 128
#define TBK 32
#define A3STR 36
#define B3STR 132
#define STAGE_F (TBM * A3STR + TBK * B3STR)
#define STAGE_BYTES (STAGE_F * 4)
#define GEMM3_SMEM (3 * STAGE_BYTES)

__global__ __launch_bounds__(256, 2) void gemm_tf32_v3(
    const float* __restrict__ A, const float* __restrict__ W,
    const float* __restrict__ bias, float* __restrict__ C,
    int M, int N, int K, int round_out)
{
    extern __shared__ float sm[];
    const uint32_t sm_u32 = (uint32_t)__cvta_generic_to_shared(sm);

    const int t    = threadIdx.x;
    const int w    = t >> 5;
    const int lane = t & 31;
    const int g    = lane >> 2;
    const int tg   = lane & 3;
    const int wm   = w >> 1;
    const int wn   = w & 1;
    const int m0   = blockIdx.y * TBM;
    const int n0   = blockIdx.x * TBN;

    const int a_row = t >> 1;
    const int a_off = (t & 1) * 16;
    const int b_row = t >> 3;
    const int b_off = (t & 7) * 16;

    const float* a_src = A + (size_t)(m0 + a_row) * K + a_off;
    const float* b_src = W + (size_t)b_row * N + n0 + b_off;
    const uint32_t a_dst = sm_u32 + (uint32_t)(a_row * A3STR + a_off) * 4u;
    const uint32_t b_dst = sm_u32 + (uint32_t)(TBM * A3STR + b_row * B3STR + b_off) * 4u;

    float acc[2][8][4];
    #pragma unroll
    for (int mi = 0; mi < 2; mi++)
        #pragma unroll
        for (int nt = 0; nt < 8; nt++)
            #pragma unroll
            for (int c = 0; c < 4; c++) acc[mi][nt][c] = 0.0f;

    const int ntiles = K / TBK;

    #pragma unroll
    for (int s = 0; s < 2; s++) {
        const int k0 = s * TBK;
        #pragma unroll
        for (int i = 0; i < 4; i++)
            cp16(a_dst + (uint32_t)s * STAGE_BYTES + i * 16, a_src + k0 + i * 4);
        #pragma unroll
        for (int i = 0; i < 4; i++)
            cp16(b_dst + (uint32_t)s * STAGE_BYTES + i * 16, b_src + (size_t)k0 * N + i * 4);
        cp_commit();
    }

    for (int kt = 0; kt < ntiles; kt++) {
        cp_wait<1>();
        __syncthreads();

        if (kt + 2 < ntiles) {
            const int s  = (kt + 2) % 3;
            const int k0 = (kt + 2) * TBK;
            #pragma unroll
            for (int i = 0; i < 4; i++)
                cp16(a_dst + (uint32_t)s * STAGE_BYTES + i * 16, a_src + k0 + i * 4);
            #pragma unroll
            for (int i = 0; i < 4; i++)
                cp16(b_dst + (uint32_t)s * STAGE_BYTES + i * 16, b_src + (size_t)k0 * N + i * 4);
        }
        cp_commit();

        const float* As = sm + (kt % 3) * STAGE_F;
        const float* Bs = As + TBM * A3STR;

        #pragma unroll
        for (int ks = 0; ks < 4; ks++) {
            uint32_t af[2][4];
            #pragma unroll
            for (int mi = 0; mi < 2; mi++) {
                const float* ab = As + (wm * 32 + mi * 16 + g) * A3STR + ks * 8 + tg;
                af[mi][0] = __float_as_uint(ab[0]);
                af[mi][1] = __float_as_uint(ab[8 * A3STR]);
                af[mi][2] = __float_as_uint(ab[4]);
                af[mi][3] = __float_as_uint(ab[8 * A3STR + 4]);
            }
            #pragma unroll
            for (int nt = 0; nt < 8; nt++) {
                const float* bb = Bs + (ks * 8 + tg) * B3STR + wn * 64 + nt * 8 + g;
                uint32_t b0 = __float_as_uint(bb[0]);
                uint32_t b1 = __float_as_uint(bb[4 * B3STR]);
                mma_tf32(acc[0][nt], af[0][0], af[0][1], af[0][2], af[0][3], b0, b1);
                mma_tf32(acc[1][nt], af[1][0], af[1][1], af[1][2], af[1][3], b0, b1);
            }
        }
    }

    #pragma unroll
    for (int mi = 0; mi < 2; mi++) {
        const int rA = m0 + wm * 32 + mi * 16 + g;
        const int rB = rA + 8;
        #pragma unroll
        for (int nt = 0; nt < 8; nt++) {
            const int col = n0 + wn * 64 + nt * 8 + tg * 2;
            float2 bb = *(const float2*)(bias + col);
            float2 vA = make_float2(acc[mi][nt][0] + bb.x, acc[mi][nt][1] + bb.y);
            float2 vB = make_float2(acc[mi][nt][2] + bb.x, acc[mi][nt][3] + bb.y);
            if (round_out) {
                vA.x = f2tf(vA.x); vA.y = f2tf(vA.y);
                vB.x = f2tf(vB.x); vB.y = f2tf(vB.y);
            }
            *(float2*)(C + (size_t)rA * N + col) = vA;
            *(float2*)(C + (size_t)rB * N + col) = vB;
        }
    }
}

// ---------------------------------------------------------------------------
// Flash attention v6: FQ=128, 256 threads (8 warps, warp owns 16 q-rows),
// BKV=64 double-buffered cp.async (prefetch distance 2), 2 CTAs/SM ->
// 16 warps/SM. Q fragments via direct LDG (one-time). exp2-domain softmax.
// smem = 2 x (64x68 + 64x72) floats = 71,680 B.
// ---------------------------------------------------------------------------
#define FQ    128
#define FBKV  64
#define KSTR  68
#define VSTR  72
#define KV_STAGE_F (FBKV * KSTR + FBKV * VSTR)     // 8960 floats
#define FLASH6_SMEM (2 * KV_STAGE_F * 4)           // 71680 bytes
#define NKB (S_LEN / FBKV)                         // 32

__global__ __launch_bounds__(256, 2) void flash_v6()
{
    extern __shared__ float sm[];
    const uint32_t sm_u32 = (uint32_t)__cvta_generic_to_shared(sm);

    const int t    = threadIdx.x;
    const int w    = t >> 5;
    const int lane = t & 31;
    const int g    = lane >> 2;
    const int tg   = lane & 3;
    const int bh   = blockIdx.y;
    const int b    = bh >> 4;
    const int h    = bh & 15;
    const int q0   = blockIdx.x * FQ;
    const int rW   = w * 16;

    // KV loader mapping: 256 threads, 4 iterations each for K and V
    const int l_r  = t >> 4;          // row base (0..15), +16*it
    const int l_c4 = (t & 15) * 4;    // col 0..60

    // ---- Q fragments via direct LDG (scaled into exp2 domain) ----
    // c = (1/sqrt(hd)) * log2(e); mma truncates low mantissa bits (tiny noise)
    const float qc = 0.125f * 1.4426950408889634f;
    uint32_t qf[8][4];
    {
        const float* qb  = g_q + (size_t)(b * S_LEN + q0 + rW + g) * DM + h * HD;
        const float* qb8 = qb + 8 * (size_t)DM;
        #pragma unroll
        for (int ks = 0; ks < 8; ks++) {
            qf[ks][0] = __float_as_uint(qb [ks * 8 + tg]     * qc);
            qf[ks][1] = __float_as_uint(qb8[ks * 8 + tg]     * qc);
            qf[ks][2] = __float_as_uint(qb [ks * 8 + tg + 4] * qc);
            qf[ks][3] = __float_as_uint(qb8[ks * 8 + tg + 4] * qc);
        }
    }

    const float* kvbase = g_kv + (size_t)(b * S_LEN) * (2 * DM) + h * 2 * HD;

    // ---- Prologue: issue KV blocks 0 and 1 ----
    #pragma unroll
    for (int s = 0; s < 2; s++) {
        const uint32_t st = sm_u32 + (uint32_t)s * (KV_STAGE_F * 4);
        const float* src = kvbase + (size_t)(s * FBKV) * (2 * DM);
        #pragma unroll
        for (int it = 0; it < 4; it++) {
            int r = l_r + 16 * it;
            const float* row = src + (size_t)r * (2 * DM);
            cp16(st + (uint32_t)(r * KSTR + l_c4) * 4u, row + l_c4);
            cp16(st + (uint32_t)(FBKV * KSTR + r * VSTR + l_c4) * 4u, row + HD + l_c4);
        }
        cp_commit();
    }

    float mA = -1e30f, mB = -1e30f, lA = 0.0f, lB = 0.0f;
    float o[8][4];
    #pragma unroll
    for (int nt = 0; nt < 8; nt++)
        #pragma unroll
        for (int c = 0; c < 4; c++) o[nt][c] = 0.0f;

    const int src1 = (lane & 0x1c) | (tg >> 1);
    const int src2 = src1 + 2;
    const bool odd = (tg & 1);

    for (int kb = 0; kb < NKB; kb++) {
        const int p = kb & 1;
        const float* Kp = sm + p * KV_STAGE_F;
        const float* Vp = Kp + FBKV * KSTR;

        cp_wait<1>();      // KV[kb] landed (only KV[kb+1] may remain pending)
        __syncthreads();

        // ---- S = Q @ K^T : 16 rows x 64 cols = 8 tiles (log2-scaled) ----
        float s[8][4];
        #pragma unroll
        for (int nt = 0; nt < 8; nt++)
            #pragma unroll
            for (int c = 0; c < 4; c++) s[nt][c] = 0.0f;

        #pragma unroll
        for (int ks = 0; ks < 8; ks++) {
            #pragma unroll
            for (int nt = 0; nt < 8; nt++) {
                const float* bb = Kp + (nt * 8 + g) * KSTR + ks * 8 + tg;
                uint32_t b0 = __float_as_uint(bb[0]);
                uint32_t b1 = __float_as_uint(bb[4]);
                mma_tf32(s[nt], qf[ks][0], qf[ks][1], qf[ks][2], qf[ks][3], b0, b1);
            }
        }

        // ---- Online softmax, exp2 domain (warp-local rows rW+g, rW+g+8) ----
        float mxA = -1e30f, mxB = -1e30f;
        #pragma unroll
        for (int nt = 0; nt < 8; nt++) {
            mxA = fmaxf(mxA, fmaxf(s[nt][0], s[nt][1]));
            mxB = fmaxf(mxB, fmaxf(s[nt][2], s[nt][3]));
        }
        mxA = fmaxf(mxA, __shfl_xor_sync(0xffffffffu, mxA, 1));
        mxA = fmaxf(mxA, __shfl_xor_sync(0xffffffffu, mxA, 2));
        mxB = fmaxf(mxB, __shfl_xor_sync(0xffffffffu, mxB, 1));
        mxB = fmaxf(mxB, __shfl_xor_sync(0xffffffffu, mxB, 2));

        const float mnA = fmaxf(mA, mxA);
        const float mnB = fmaxf(mB, mxB);
        const float aA  = exp2f(mA - mnA);
        const float aB  = exp2f(mB - mnB);
        mA = mnA; mB = mnB;

        float sumA = 0.0f, sumB = 0.0f;
        #pragma unroll
        for (int nt = 0; nt < 8; nt++) {
            float e0 = exp2f(s[nt][0] - mnA);
            float e1 = exp2f(s[nt][1] - mnA);
            float e2 = exp2f(s[nt][2] - mnB);
            float e3 = exp2f(s[nt][3] - mnB);
            sumA += e0 + e1;
            sumB += e2 + e3;
            s[nt][0] = f2tf(e0); s[nt][1] = f2tf(e1);
            s[nt][2] = f2tf(e2); s[nt][3] = f2tf(e3);
        }
        sumA += __shfl_xor_sync(0xffffffffu, sumA, 1);
        sumA += __shfl_xor_sync(0xffffffffu, sumA, 2);
        sumB += __shfl_xor_sync(0xffffffffu, sumB, 1);
        sumB += __shfl_xor_sync(0xffffffffu, sumB, 2);
        lA = lA * aA + sumA;
        lB = lB * aB + sumB;

        #pragma unroll
        for (int nt = 0; nt < 8; nt++) {
            o[nt][0] *= aA; o[nt][1] *= aA;
            o[nt][2] *= aB; o[nt][3] *= aB;
        }

        // ---- O += P @ V : A-fragments via warp shuffles ----
        #pragma unroll
        for (int ksp = 0; ksp < 8; ksp++) {
            float v00 = __shfl_sync(0xffffffffu, s[ksp][0], src1);
            float v01 = __shfl_sync(0xffffffffu, s[ksp][1], src1);
            float v02 = __shfl_sync(0xffffffffu, s[ksp][2], src1);
            float v03 = __shfl_sync(0xffffffffu, s[ksp][3], src1);
            float v10 = __shfl_sync(0xffffffffu, s[ksp][0], src2);
            float v11 = __shfl_sync(0xffffffffu, s[ksp][1], src2);
            float v12 = __shfl_sync(0xffffffffu, s[ksp][2], src2);
            float v13 = __shfl_sync(0xffffffffu, s[ksp][3], src2);
            uint32_t a0 = __float_as_uint(odd ? v01 : v00);
            uint32_t a1 = __float_as_uint(odd ? v03 : v02);
            uint32_t a2 = __float_as_uint(odd ? v11 : v10);
            uint32_t a3 = __float_as_uint(odd ? v13 : v12);
            #pragma unroll
            for (int nt = 0; nt < 8; nt++) {
                const float* vb = Vp + (ksp * 8 + tg) * VSTR + nt * 8 + g;
                uint32_t b0 = __float_as_uint(vb[0]);
                uint32_t b1 = __float_as_uint(vb[4 * VSTR]);
                mma_tf32(o[nt], a0, a1, a2, a3, b0, b1);
            }
        }

        __syncthreads();   // all warps done with stage p before overwrite

        // ---- Prefetch KV[kb+2] into stage p ----
        if (kb + 2 < NKB) {
            const uint32_t st = sm_u32 + (uint32_t)p * (KV_STAGE_F * 4);
            const float* src = kvbase + (size_t)((kb + 2) * FBKV) * (2 * DM);
            #pragma unroll
            for (int it = 0; it < 4; it++) {
                int r = l_r + 16 * it;
                const float* row = src + (size_t)r * (2 * DM);
                cp16(st + (uint32_t)(r * KSTR + l_c4) * 4u, row + l_c4);
                cp16(st + (uint32_t)(FBKV * KSTR + r * VSTR + l_c4) * 4u, row + HD + l_c4);
            }
        }
        cp_commit();   // real or empty: keeps group accounting uniform
    }

    // ---- Normalize + write out (tf32-rounded: consumed by final GEMM) ----
    const float invA = 1.0f / lA;
    const float invB = 1.0f / lB;
    float* obaseA = g_att + (size_t)(b * S_LEN + q0 + rW + g) * DM + h * HD;
    float* obaseB = obaseA + 8 * (size_t)DM;
    #pragma unroll
    for (int nt = 0; nt < 8; nt++) {
        const int col = nt * 8 + tg * 2;
        *(float2*)(obaseA + col) = make_float2(f2tf(o[nt][0] * invA), f2tf(o[nt][1] * invA));
        *(float2*)(obaseB + col) = make_float2(f2tf(o[nt][2] * invB), f2tf(o[nt][3] * invB));
    }
}

// ---------------------------------------------------------------------------
// Host launcher (graph-capturable: kernel launches only)
// ---------------------------------------------------------------------------
extern "C" void kernel_launch(void* const* d_in, const int* in_sizes, int n_in,
                              void* d_out, int out_size)
{
    const float* x   = (const float*)d_in[0];
    const float* y   = (const float*)d_in[1];
    const float* Wkv = (const float*)d_in[2];
    const float* bkv = (const float*)d_in[3];
    const float* Wq  = (const float*)d_in[4];
    const float* bq  = (const float*)d_in[5];
    const float* Wo  = (const float*)d_in[6];
    const float* bo  = (const float*)d_in[7];
    float* out = (float*)d_out;

    float *kv, *q, *att, *xt, *yt, *wkvt, *wqt, *wot;
    cudaGetSymbolAddress((void**)&kv,   g_kv);
    cudaGetSymbolAddress((void**)&q,    g_q);
    cudaGetSymbolAddress((void**)&att,  g_att);
    cudaGetSymbolAddress((void**)&xt,   g_xt);
    cudaGetSymbolAddress((void**)&yt,   g_yt);
    cudaGetSymbolAddress((void**)&wkvt, g_wkvt);
    cudaGetSymbolAddress((void**)&wqt,  g_wqt);
    cudaGetSymbolAddress((void**)&wot,  g_wot);

    cudaFuncSetAttribute(gemm_tf32_v3,
                         cudaFuncAttributeMaxDynamicSharedMemorySize, GEMM3_SMEM);
    cudaFuncSetAttribute(flash_v6,
                         cudaFuncAttributeMaxDynamicSharedMemorySize, FLASH6_SMEM);

    dim3 blk(256);

    conv_all<<<2048, 256>>>(
        (const float4*)x, (const float4*)y, (const float4*)Wkv,
        (const float4*)Wq, (const float4*)Wo,
        (float4*)xt, (float4*)yt, (float4*)wkvt, (float4*)wqt, (float4*)wot);

    gemm_tf32_v3<<<dim3(2 * DM / TBN, MROWS / TBM), blk, GEMM3_SMEM>>>(
        xt, wkvt, bkv, kv, MROWS, 2 * DM, DM, 1);
    gemm_tf32_v3<<<dim3(DM / TBN, MROWS / TBM), blk, GEMM3_SMEM>>>(
        yt, wqt, bq, q, MROWS, DM, DM, 1);
    flash_v6<<<dim3(S_LEN / FQ, BATCH * NHEAD), blk, FLASH6_SMEM>>>();
    gemm_tf32_v3<<<dim3(DM / TBN, MROWS / TBM), blk, GEMM3_SMEM>>>(
        att, wot, bo, out, MROWS, DM, DM, 0);
}

// round 9
// speedup vs baseline: 1.0803x; 1.0803x over previous
#include <cuda_runtime.h>
#include <cstdint>

// Problem constants
#define S_LEN 2048
#define BATCH 2
#define NHEAD 16
#define HD    64
#define DM    1024
#define MROWS (BATCH * S_LEN)   // 4096

// Scratch (device globals: no allocations allowed)
__device__ float g_kv [MROWS * 2 * DM];   // k,v projections (tf32-rounded)
__device__ float g_q  [MROWS * DM];       // q projection   (tf32-rounded)
__device__ float g_att[MROWS * DM];       // attention out  (tf32-rounded)
__device__ float g_xt [MROWS * DM];       // tf32(x)
__device__ float g_yt [MROWS * DM];       // tf32(y)
__device__ float g_wkvt[DM * 2 * DM];     // tf32(Wkv)
__device__ float g_wqt [DM * DM];         // tf32(Wq)
__device__ float g_wot [DM * DM];         // tf32(Wo)

// ---------------------------------------------------------------------------
// helpers
// ---------------------------------------------------------------------------
__device__ __forceinline__ float f2tf(float x) {
    uint32_t r;
    asm("cvt.rna.tf32.f32 %0, %1;" : "=r"(r) : "f"(x));
    return __uint_as_float(r);
}

__device__ __forceinline__ void mma_tf32(float c[4],
                                         uint32_t a0, uint32_t a1, uint32_t a2, uint32_t a3,
                                         uint32_t b0, uint32_t b1) {
    asm volatile(
        "mma.sync.aligned.m16n8k8.row.col.f32.tf32.tf32.f32 "
        "{%0,%1,%2,%3}, {%4,%5,%6,%7}, {%8,%9}, {%0,%1,%2,%3};"
        : "+f"(c[0]), "+f"(c[1]), "+f"(c[2]), "+f"(c[3])
        : "r"(a0), "r"(a1), "r"(a2), "r"(a3), "r"(b0), "r"(b1));
}

__device__ __forceinline__ void cp16(uint32_t dst, const float* src) {
    asm volatile("cp.async.cg.shared.global [%0], [%1], 16;" :: "r"(dst), "l"(src));
}
__device__ __forceinline__ void cp_commit() {
    asm volatile("cp.async.commit_group;");
}
template<int N> __device__ __forceinline__ void cp_wait() {
    asm volatile("cp.async.wait_group %0;" :: "n"(N));
}

// ---------------------------------------------------------------------------
// Merged tf32 conversion pass (one launch for all 5 tensors)
// ---------------------------------------------------------------------------
#define N4_X  (MROWS * DM / 4)
#define N4_Y  (MROWS * DM / 4)
#define N4_KV (DM * 2 * DM / 4)
#define N4_Q  (DM * DM / 4)
#define N4_O  (DM * DM / 4)
#define N4_TOT (N4_X + N4_Y + N4_KV + N4_Q + N4_O)

__global__ void conv_all(
    const float4* __restrict__ x,  const float4* __restrict__ y,
    const float4* __restrict__ wkv, const float4* __restrict__ wq,
    const float4* __restrict__ wo,
    float4* __restrict__ xt,  float4* __restrict__ yt,
    float4* __restrict__ wkvt, float4* __restrict__ wqt,
    float4* __restrict__ wot)
{
    int i = blockIdx.x * blockDim.x + threadIdx.x;
    const int stride = gridDim.x * blockDim.x;
    for (; i < N4_TOT; i += stride) {
        const float4* src; float4* dst; int j = i;
        if (j < N4_X)                  { src = x;   dst = xt;   }
        else if ((j -= N4_X)  < N4_Y)  { src = y;   dst = yt;   }
        else if ((j -= N4_Y)  < N4_KV) { src = wkv; dst = wkvt; }
        else if ((j -= N4_KV) < N4_Q)  { src = wq;  dst = wqt;  }
        else { j -= N4_Q;                src = wo;  dst = wot;  }
        float4 v = src[j];
        dst[j] = make_float4(f2tf(v.x), f2tf(v.y), f2tf(v.z), f2tf(v.w));
    }
}

// ---------------------------------------------------------------------------
// GEMM v4: C[M,N] = A[M,K] @ W[K,N] + bias[N]   (A, W already tf32-rounded)
// CTA 128x128, 128 threads (4 warps, 2m x 2n), warp tile 64x64
// (4 m16 x 8 n8 tiles = 32 mma per k-slice; LDS/mma = 1.0).
// BK=32, 3-stage cp.async pipeline, 2 CTAs/SM.
// As [128][36] (36==4 mod 32); Bs [32][132] (132==4 mod 32).
// ---------------------------------------------------------------------------
#define TBM 128
#define TBN 128
#define TBK 32
#define A4STR 36
#define B4STR 132
#define STAGE_F (TBM * A4STR + TBK * B4STR)   // 8832 floats
#define STAGE_BYTES (STAGE_F * 4)             // 35328
#define GEMM4_SMEM (3 * STAGE_BYTES)          // 105984

__global__ __launch_bounds__(128, 2) void gemm_tf32_v4(
    const float* __restrict__ A, const float* __restrict__ W,
    const float* __restrict__ bias, float* __restrict__ C,
    int M, int N, int K, int round_out)
{
    extern __shared__ float sm[];
    const uint32_t sm_u32 = (uint32_t)__cvta_generic_to_shared(sm);

    const int t    = threadIdx.x;
    const int w    = t >> 5;
    const int lane = t & 31;
    const int g    = lane >> 2;
    const int tg   = lane & 3;
    const int wm   = w >> 1;     // 0..1
    const int wn   = w & 1;      // 0..1
    const int m0   = blockIdx.y * TBM;
    const int n0   = blockIdx.x * TBN;

    // loader mapping (128 threads):
    // A tile 128x32: thread t -> row t, 8 float4 (cols it*4)
    // B tile 32x128: thread t -> row t>>2, float4 cols (t&3)+4*it (it 0..7)
    const int b_row = t >> 2;
    const int b_c   = t & 3;

    const float* a_src = A + (size_t)(m0 + t) * K;
    const float* b_src = W + (size_t)b_row * N + n0;
    const uint32_t a_dst = sm_u32 + (uint32_t)(t * A4STR) * 4u;
    const uint32_t b_dst = sm_u32 + (uint32_t)(TBM * A4STR + b_row * B4STR) * 4u;

    float acc[4][8][4];
    #pragma unroll
    for (int mi = 0; mi < 4; mi++)
        #pragma unroll
        for (int nt = 0; nt < 8; nt++)
            #pragma unroll
            for (int c = 0; c < 4; c++) acc[mi][nt][c] = 0.0f;

    const int ntiles = K / TBK;

    // prologue: stages 0,1
    #pragma unroll
    for (int s = 0; s < 2; s++) {
        const int k0 = s * TBK;
        #pragma unroll
        for (int i = 0; i < 8; i++)
            cp16(a_dst + (uint32_t)s * STAGE_BYTES + i * 16, a_src + k0 + i * 4);
        #pragma unroll
        for (int i = 0; i < 8; i++) {
            int c4 = b_c + 4 * i;
            cp16(b_dst + (uint32_t)s * STAGE_BYTES + (uint32_t)c4 * 16,
                 b_src + (size_t)k0 * N + c4 * 4);
        }
        cp_commit();
    }

    for (int kt = 0; kt < ntiles; kt++) {
        cp_wait<1>();
        __syncthreads();

        if (kt + 2 < ntiles) {
            const int s  = (kt + 2) % 3;
            const int k0 = (kt + 2) * TBK;
            #pragma unroll
            for (int i = 0; i < 8; i++)
                cp16(a_dst + (uint32_t)s * STAGE_BYTES + i * 16, a_src + k0 + i * 4);
            #pragma unroll
            for (int i = 0; i < 8; i++) {
                int c4 = b_c + 4 * i;
                cp16(b_dst + (uint32_t)s * STAGE_BYTES + (uint32_t)c4 * 16,
                     b_src + (size_t)k0 * N + c4 * 4);
            }
        }
        cp_commit();

        const float* As = sm + (kt % 3) * STAGE_F;
        const float* Bs = As + TBM * A4STR;

        #pragma unroll
        for (int ks = 0; ks < 4; ks++) {
            uint32_t af[4][4];
            #pragma unroll
            for (int mi = 0; mi < 4; mi++) {
                const float* ab = As + (wm * 64 + mi * 16 + g) * A4STR + ks * 8 + tg;
                af[mi][0] = __float_as_uint(ab[0]);
                af[mi][1] = __float_as_uint(ab[8 * A4STR]);
                af[mi][2] = __float_as_uint(ab[4]);
                af[mi][3] = __float_as_uint(ab[8 * A4STR + 4]);
            }
            #pragma unroll
            for (int nt = 0; nt < 8; nt++) {
                const float* bb = Bs + (ks * 8 + tg) * B4STR + wn * 64 + nt * 8 + g;
                uint32_t b0 = __float_as_uint(bb[0]);
                uint32_t b1 = __float_as_uint(bb[4 * B4STR]);
                #pragma unroll
                for (int mi = 0; mi < 4; mi++)
                    mma_tf32(acc[mi][nt], af[mi][0], af[mi][1], af[mi][2], af[mi][3], b0, b1);
            }
        }
    }

    // epilogue
    #pragma unroll
    for (int mi = 0; mi < 4; mi++) {
        const int rA = m0 + wm * 64 + mi * 16 + g;
        const int rB = rA + 8;
        #pragma unroll
        for (int nt = 0; nt < 8; nt++) {
            const int col = n0 + wn * 64 + nt * 8 + tg * 2;
            float2 bb = *(const float2*)(bias + col);
            float2 vA = make_float2(acc[mi][nt][0] + bb.x, acc[mi][nt][1] + bb.y);
            float2 vB = make_float2(acc[mi][nt][2] + bb.x, acc[mi][nt][3] + bb.y);
            if (round_out) {
                vA.x = f2tf(vA.x); vA.y = f2tf(vA.y);
                vB.x = f2tf(vB.x); vB.y = f2tf(vB.y);
            }
            *(float2*)(C + (size_t)rA * N + col) = vA;
            *(float2*)(C + (size_t)rB * N + col) = vB;
        }
    }
}

// ---------------------------------------------------------------------------
// Flash attention v6 (numerics fixed): FQ=128, 256 threads, BKV=64
// double-buffered cp.async, 2 CTAs/SM. Q scale exact 0.125; exponentials via
// exp2f(fma(s, log2e, -m*log2e)).
// ---------------------------------------------------------------------------
#define FQ    128
#define FBKV  64
#define KSTR  68
#define VSTR  72
#define KV_STAGE_F (FBKV * KSTR + FBKV * VSTR)     // 8960 floats
#define FLASH6_SMEM (2 * KV_STAGE_F * 4)           // 71680 bytes
#define NKB (S_LEN / FBKV)                         // 32

__global__ __launch_bounds__(256, 2) void flash_v6()
{
    extern __shared__ float sm[];
    const uint32_t sm_u32 = (uint32_t)__cvta_generic_to_shared(sm);

    const int t    = threadIdx.x;
    const int w    = t >> 5;
    const int lane = t & 31;
    const int g    = lane >> 2;
    const int tg   = lane & 3;
    const int bh   = blockIdx.y;
    const int b    = bh >> 4;
    const int h    = bh & 15;
    const int q0   = blockIdx.x * FQ;
    const int rW   = w * 16;
    const float L2E = 1.4426950408889634f;

    const int l_r  = t >> 4;
    const int l_c4 = (t & 15) * 4;

    // ---- Q fragments via direct LDG (exact 0.125 scale) ----
    uint32_t qf[8][4];
    {
        const float* qb  = g_q + (size_t)(b * S_LEN + q0 + rW + g) * DM + h * HD;
        const float* qb8 = qb + 8 * (size_t)DM;
        #pragma unroll
        for (int ks = 0; ks < 8; ks++) {
            qf[ks][0] = __float_as_uint(qb [ks * 8 + tg]     * 0.125f);
            qf[ks][1] = __float_as_uint(qb8[ks * 8 + tg]     * 0.125f);
            qf[ks][2] = __float_as_uint(qb [ks * 8 + tg + 4] * 0.125f);
            qf[ks][3] = __float_as_uint(qb8[ks * 8 + tg + 4] * 0.125f);
        }
    }

    const float* kvbase = g_kv + (size_t)(b * S_LEN) * (2 * DM) + h * 2 * HD;

    // ---- Prologue: issue KV blocks 0 and 1 ----
    #pragma unroll
    for (int s = 0; s < 2; s++) {
        const uint32_t st = sm_u32 + (uint32_t)s * (KV_STAGE_F * 4);
        const float* src = kvbase + (size_t)(s * FBKV) * (2 * DM);
        #pragma unroll
        for (int it = 0; it < 4; it++) {
            int r = l_r + 16 * it;
            const float* row = src + (size_t)r * (2 * DM);
            cp16(st + (uint32_t)(r * KSTR + l_c4) * 4u, row + l_c4);
            cp16(st + (uint32_t)(FBKV * KSTR + r * VSTR + l_c4) * 4u, row + HD + l_c4);
        }
        cp_commit();
    }

    float mA = -1e30f, mB = -1e30f, lA = 0.0f, lB = 0.0f;
    float o[8][4];
    #pragma unroll
    for (int nt = 0; nt < 8; nt++)
        #pragma unroll
        for (int c = 0; c < 4; c++) o[nt][c] = 0.0f;

    const int src1 = (lane & 0x1c) | (tg >> 1);
    const int src2 = src1 + 2;
    const bool odd = (tg & 1);

    for (int kb = 0; kb < NKB; kb++) {
        const int p = kb & 1;
        const float* Kp = sm + p * KV_STAGE_F;
        const float* Vp = Kp + FBKV * KSTR;

        cp_wait<1>();
        __syncthreads();

        // ---- S = Q @ K^T ----
        float s[8][4];
        #pragma unroll
        for (int nt = 0; nt < 8; nt++)
            #pragma unroll
            for (int c = 0; c < 4; c++) s[nt][c] = 0.0f;

        #pragma unroll
        for (int ks = 0; ks < 8; ks++) {
            #pragma unroll
            for (int nt = 0; nt < 8; nt++) {
                const float* bb = Kp + (nt * 8 + g) * KSTR + ks * 8 + tg;
                uint32_t b0 = __float_as_uint(bb[0]);
                uint32_t b1 = __float_as_uint(bb[4]);
                mma_tf32(s[nt], qf[ks][0], qf[ks][1], qf[ks][2], qf[ks][3], b0, b1);
            }
        }

        // ---- Online softmax (natural-domain max, exp2+fma exponentials) ----
        float mxA = -1e30f, mxB = -1e30f;
        #pragma unroll
        for (int nt = 0; nt < 8; nt++) {
            mxA = fmaxf(mxA, fmaxf(s[nt][0], s[nt][1]));
            mxB = fmaxf(mxB, fmaxf(s[nt][2], s[nt][3]));
        }
        mxA = fmaxf(mxA, __shfl_xor_sync(0xffffffffu, mxA, 1));
        mxA = fmaxf(mxA, __shfl_xor_sync(0xffffffffu, mxA, 2));
        mxB = fmaxf(mxB, __shfl_xor_sync(0xffffffffu, mxB, 1));
        mxB = fmaxf(mxB, __shfl_xor_sync(0xffffffffu, mxB, 2));

        const float mnA = fmaxf(mA, mxA);
        const float mnB = fmaxf(mB, mxB);
        const float aA  = exp2f((mA - mnA) * L2E);
        const float aB  = exp2f((mB - mnB) * L2E);
        mA = mnA; mB = mnB;

        const float mnAl = mnA * L2E;
        const float mnBl = mnB * L2E;
        float sumA = 0.0f, sumB = 0.0f;
        #pragma unroll
        for (int nt = 0; nt < 8; nt++) {
            float e0 = exp2f(fmaf(s[nt][0], L2E, -mnAl));
            float e1 = exp2f(fmaf(s[nt][1], L2E, -mnAl));
            float e2 = exp2f(fmaf(s[nt][2], L2E, -mnBl));
            float e3 = exp2f(fmaf(s[nt][3], L2E, -mnBl));
            sumA += e0 + e1;
            sumB += e2 + e3;
            s[nt][0] = f2tf(e0); s[nt][1] = f2tf(e1);
            s[nt][2] = f2tf(e2); s[nt][3] = f2tf(e3);
        }
        sumA += __shfl_xor_sync(0xffffffffu, sumA, 1);
        sumA += __shfl_xor_sync(0xffffffffu, sumA, 2);
        sumB += __shfl_xor_sync(0xffffffffu, sumB, 1);
        sumB += __shfl_xor_sync(0xffffffffu, sumB, 2);
        lA = lA * aA + sumA;
        lB = lB * aB + sumB;

        #pragma unroll
        for (int nt = 0; nt < 8; nt++) {
            o[nt][0] *= aA; o[nt][1] *= aA;
            o[nt][2] *= aB; o[nt][3] *= aB;
        }

        // ---- O += P @ V ----
        #pragma unroll
        for (int ksp = 0; ksp < 8; ksp++) {
            float v00 = __shfl_sync(0xffffffffu, s[ksp][0], src1);
            float v01 = __shfl_sync(0xffffffffu, s[ksp][1], src1);
            float v02 = __shfl_sync(0xffffffffu, s[ksp][2], src1);
            float v03 = __shfl_sync(0xffffffffu, s[ksp][3], src1);
            float v10 = __shfl_sync(0xffffffffu, s[ksp][0], src2);
            float v11 = __shfl_sync(0xffffffffu, s[ksp][1], src2);
            float v12 = __shfl_sync(0xffffffffu, s[ksp][2], src2);
            float v13 = __shfl_sync(0xffffffffu, s[ksp][3], src2);
            uint32_t a0 = __float_as_uint(odd ? v01 : v00);
            uint32_t a1 = __float_as_uint(odd ? v03 : v02);
            uint32_t a2 = __float_as_uint(odd ? v11 : v10);
            uint32_t a3 = __float_as_uint(odd ? v13 : v12);
            #pragma unroll
            for (int nt = 0; nt < 8; nt++) {
                const float* vb = Vp + (ksp * 8 + tg) * VSTR + nt * 8 + g;
                uint32_t b0 = __float_as_uint(vb[0]);
                uint32_t b1 = __float_as_uint(vb[4 * VSTR]);
                mma_tf32(o[nt], a0, a1, a2, a3, b0, b1);
            }
        }

        __syncthreads();

        // ---- Prefetch KV[kb+2] into stage p ----
        if (kb + 2 < NKB) {
            const uint32_t st = sm_u32 + (uint32_t)p * (KV_STAGE_F * 4);
            const float* src = kvbase + (size_t)((kb + 2) * FBKV) * (2 * DM);
            #pragma unroll
            for (int it = 0; it < 4; it++) {
                int r = l_r + 16 * it;
                const float* row = src + (size_t)r * (2 * DM);
                cp16(st + (uint32_t)(r * KSTR + l_c4) * 4u, row + l_c4);
                cp16(st + (uint32_t)(FBKV * KSTR + r * VSTR + l_c4) * 4u, row + HD + l_c4);
            }
        }
        cp_commit();
    }

    // ---- Normalize + write out ----
    const float invA = 1.0f / lA;
    const float invB = 1.0f / lB;
    float* obaseA = g_att + (size_t)(b * S_LEN + q0 + rW + g) * DM + h * HD;
    float* obaseB = obaseA + 8 * (size_t)DM;
    #pragma unroll
    for (int nt = 0; nt < 8; nt++) {
        const int col = nt * 8 + tg * 2;
        *(float2*)(obaseA + col) = make_float2(f2tf(o[nt][0] * invA), f2tf(o[nt][1] * invA));
        *(float2*)(obaseB + col) = make_float2(f2tf(o[nt][2] * invB), f2tf(o[nt][3] * invB));
    }
}

// ---------------------------------------------------------------------------
// Host launcher (graph-capturable: kernel launches only)
// ---------------------------------------------------------------------------
extern "C" void kernel_launch(void* const* d_in, const int* in_sizes, int n_in,
                              void* d_out, int out_size)
{
    const float* x   = (const float*)d_in[0];
    const float* y   = (const float*)d_in[1];
    const float* Wkv = (const float*)d_in[2];
    const float* bkv = (const float*)d_in[3];
    const float* Wq  = (const float*)d_in[4];
    const float* bq  = (const float*)d_in[5];
    const float* Wo  = (const float*)d_in[6];
    const float* bo  = (const float*)d_in[7];
    float* out = (float*)d_out;

    float *kv, *q, *att, *xt, *yt, *wkvt, *wqt, *wot;
    cudaGetSymbolAddress((void**)&kv,   g_kv);
    cudaGetSymbolAddress((void**)&q,    g_q);
    cudaGetSymbolAddress((void**)&att,  g_att);
    cudaGetSymbolAddress((void**)&xt,   g_xt);
    cudaGetSymbolAddress((void**)&yt,   g_yt);
    cudaGetSymbolAddress((void**)&wkvt, g_wkvt);
    cudaGetSymbolAddress((void**)&wqt,  g_wqt);
    cudaGetSymbolAddress((void**)&wot,  g_wot);

    cudaFuncSetAttribute(gemm_tf32_v4,
                         cudaFuncAttributeMaxDynamicSharedMemorySize, GEMM4_SMEM);
    cudaFuncSetAttribute(flash_v6,
                         cudaFuncAttributeMaxDynamicSharedMemorySize, FLASH6_SMEM);

    conv_all<<<2048, 256>>>(
        (const float4*)x, (const float4*)y, (const float4*)Wkv,
        (const float4*)Wq, (const float4*)Wo,
        (float4*)xt, (float4*)yt, (float4*)wkvt, (float4*)wqt, (float4*)wot);

    gemm_tf32_v4<<<dim3(2 * DM / TBN, MROWS / TBM), 128, GEMM4_SMEM>>>(
        xt, wkvt, bkv, kv, MROWS, 2 * DM, DM, 1);
    gemm_tf32_v4<<<dim3(DM / TBN, MROWS / TBM), 128, GEMM4_SMEM>>>(
        yt, wqt, bq, q, MROWS, DM, DM, 1);
    flash_v6<<<dim3(S_LEN / FQ, BATCH * NHEAD), 256, FLASH6_SMEM>>>();
    gemm_tf32_v4<<<dim3(DM / TBN, MROWS / TBM), 128, GEMM4_SMEM>>>(
        att, wot, bo, out, MROWS, DM, DM, 0);
}